// round 14
// baseline (speedup 1.0000x reference)
#include <cuda_runtime.h>
#include <cstdint>

#define D 128
#define C 64
#define EPSF 1e-5f
#define TGT 16              // targets per CTA -> grid = 16384/16 = 1024
#define XS_STRIDE 132       // conflict-free row stride

// q[c][j] = EPS - prototype[c][j]   (device scratch; allocations forbidden)
__device__ float g_q[C * D];

__device__ __forceinline__ void add_f32x2(unsigned long long& d,
                                          unsigned long long a,
                                          unsigned long long b) {
    asm("add.rn.f32x2 %0, %1, %2;" : "=l"(d) : "l"(a), "l"(b));
}
__device__ __forceinline__ void unpack2(float& lo, float& hi,
                                        unsigned long long v) {
    asm("mov.b64 {%0, %1}, %2;" : "=f"(lo), "=f"(hi) : "l"(v));
}

// ---------------------------------------------------------------------------
// Kernel 1 (R12-proven): one CTA per class, block 512 = 4 row-streams.
// Gather row list (unrolled scan), 4 parallel accumulation streams, unroll 8.
// Writes q = EPS - sum/cnt'. CTA0 zeroes out.
// ---------------------------------------------------------------------------
__global__ __launch_bounds__(512) void k_accum(const float* __restrict__ x,
                                               const int* __restrict__ y,
                                               float* __restrict__ out,
                                               int m) {
    __shared__ unsigned short list[4096];
    __shared__ int cnt;
    __shared__ float partial[4 * D];

    int tid = threadIdx.x;
    int c   = blockIdx.x;
    if (tid == 0) cnt = 0;
    if (c == 0 && tid == 0) out[0] = 0.0f;
    __syncthreads();

#pragma unroll 8
    for (int i = tid; i < m; i += 512) {
        if (y[i] == c) {
            int p = atomicAdd(&cnt, 1);
            if (p < 4096) list[p] = (unsigned short)i;
        }
    }
    __syncthreads();
    int n = cnt < 4096 ? cnt : 4096;

    int j  = tid & (D - 1);
    int st = tid >> 7;                 // stream 0..3
    float acc = 0.0f;
#pragma unroll 8
    for (int k = st; k < n; k += 4) {
        acc += x[(size_t)list[k] * D + j];
    }
    partial[st * D + j] = acc;
    __syncthreads();
    if (tid < D) {
        float tot = partial[j] + partial[D + j] + partial[2 * D + j]
                  + partial[3 * D + j];
        float fc  = (n == 0) ? 1.0f : (float)n;
        g_q[c * D + j] = EPSF - tot / fc;
    }
}

// ---------------------------------------------------------------------------
// Kernel 2: distances + log_softmax + NLL. R10 math (1.5 fma-instr/el),
// re-tiled for balance + occupancy:
// block 256 = 8 warps; warp w: classes [8w, 8w+8); lane = sub*16 + trow;
// each lane: 1 target (trow), 4 classes (8w+4sub..+3).
// Per j4 per warp: 1 x-LDS (2-way bcast) + 4 q-LDS (full bcast) per 512 el.
// smem ~43KB, <=51 regs -> 5 CTAs/SM (40 warps); grid 1024 -> ~1% imbalance.
// ---------------------------------------------------------------------------
extern __shared__ float dynsmem[];

__global__ __launch_bounds__(256, 5) void k_loss(const float* __restrict__ x,
                                                 const int* __restrict__ y,
                                                 float* __restrict__ out,
                                                 int m) {
    float* xs = dynsmem;                   // 16 * 132 =  8.4 KB
    float* qs = xs + TGT * XS_STRIDE;      // 64 * 128 = 32   KB
    __shared__ float spmax[16 * TGT];
    __shared__ float spsum[16 * TGT];
    __shared__ float sdy[TGT];

    int tid = threadIdx.x;
    int i0  = blockIdx.x * TGT;

    // stage x target tile (16 x 128, coalesced float4)
    const float4* xg = (const float4*)(x + (size_t)(m + i0) * D);
#pragma unroll
    for (int k = 0; k < 2; k++) {
        int idx = tid + k * 256;           // 0..511
        int r = idx >> 5, c4 = idx & 31;
        *(float4*)&xs[r * XS_STRIDE + c4 * 4] = xg[r * 32 + c4];
    }
    // stage q (L2-resident)
#pragma unroll
    for (int k = 0; k < 8; k++) {
        int idx = tid + k * 256;           // 0..2047 float4
        ((float4*)qs)[idx] = ((const float4*)g_q)[idx];
    }
    __syncthreads();

    int lane = tid & 31;
    int cg   = tid >> 5;                  // warp id 0..7
    int sub  = lane >> 4;                 // 0/1: class sub-group
    int trow = lane & 15;                 // target 0..15
    int cb   = cg * 8 + sub * 4;          // first of this lane's 4 classes
    int sidx = cg * 2 + sub;              // class-subset index 0..15

    const ulonglong2* xr = (const ulonglong2*)&xs[trow * XS_STRIDE];
    const float* qb = &qs[cb * D];

    float acc[4];
#pragma unroll
    for (int k = 0; k < 4; k++) acc[k] = 0.0f;

#pragma unroll 2
    for (int j4 = 0; j4 < D / 4; j4++) {
        ulonglong2 xv = xr[j4];
#pragma unroll
        for (int cc = 0; cc < 4; cc++) {
            ulonglong2 qv = *(const ulonglong2*)&qb[cc * D + j4 * 4];
            unsigned long long a, b;
            add_f32x2(a, xv.x, qv.x);      // t = x + (EPS - p), dims 0-1
            add_f32x2(b, xv.y, qv.y);      // dims 2-3
            float lo, hi;
            unpack2(lo, hi, a);
            acc[cc] = fmaf(lo, fabsf(lo), acc[cc]);   // sign(t)*t^2
            acc[cc] = fmaf(hi, fabsf(hi), acc[cc]);
            unpack2(lo, hi, b);
            acc[cc] = fmaf(lo, fabsf(lo), acc[cc]);
            acc[cc] = fmaf(hi, fabsf(hi), acc[cc]);
        }
    }

    // partial softmax over this lane's 4 classes
    float dist[4];
    float pm = -1e30f;
#pragma unroll
    for (int cc = 0; cc < 4; cc++) {
        float dv = acc[cc] * (-1.0f / (float)D);
        dist[cc] = dv;
        pm = fmaxf(pm, dv);
    }
    spmax[sidx * TGT + trow] = pm;
    __syncthreads();

    float gm = -1e30f;
#pragma unroll
    for (int k = 0; k < 16; k++) gm = fmaxf(gm, spmax[k * TGT + trow]);

    float se = 0.0f;
#pragma unroll
    for (int cc = 0; cc < 4; cc++) se += __expf(dist[cc] - gm);
    spsum[sidx * TGT + trow] = se;

    int yc = y[m + i0 + trow];
    if (yc >= cb && yc < cb + 4) sdy[trow] = dist[yc - cb];
    __syncthreads();

    if (tid < TGT) {
        float tot = 0.0f, g2 = -1e30f;
#pragma unroll
        for (int k = 0; k < 16; k++) {
            tot += spsum[k * TGT + tid];
            g2   = fmaxf(g2, spmax[k * TGT + tid]);
        }
        float v = -(sdy[tid] - g2 - __logf(tot));
#pragma unroll
        for (int off = 8; off > 0; off >>= 1)
            v += __shfl_xor_sync(0x0000FFFFu, v, off);
        if (tid == 0) atomicAdd(out, v / (float)m);
    }
}

// ---------------------------------------------------------------------------
// launch
// ---------------------------------------------------------------------------
extern "C" void kernel_launch(void* const* d_in, const int* in_sizes, int n_in,
                              void* d_out, int out_size) {
    const float* x = (const float*)d_in[0];
    const int*   y = (const int*)d_in[1];
    int n = in_sizes[1];
    int m = n / 2;
    float* out = (float*)d_out;

    k_accum<<<C, 512>>>(x, y, out, m);

    size_t dynbytes = (size_t)(TGT * XS_STRIDE + C * D) * sizeof(float);
    cudaFuncSetAttribute(k_loss, cudaFuncAttributeMaxDynamicSharedMemorySize,
                         (int)dynbytes);
    k_loss<<<m / TGT, 256, dynbytes>>>(x, y, out, m);
}